// round 5
// baseline (speedup 1.0000x reference)
#include <cuda_runtime.h>
#include <cstdint>

#define B_    1024
#define NIT   100000
#define NC    10
#define D_    64
#define IT    256                 // items per chunk
#define NCH   404                 // max chunks (sum ceil(cnt/256) <= 401)
#define NPAD  (NCH*IT)            // 103424 padded items
#define UT    64                  // users per CTA in main kernel
#define KS    8                   // k rows staged per phase

// ---------------- device scratch (static, no runtime allocation) ----------------
__device__ float g_S1[NC*D_];                    // cluster-summed W1  (10 x 64)
__device__ int   g_icounts[NC];
__device__ int   g_cursor[NC];
__device__ float g_E[B_*NC];                     // per-(user,cluster) exp sums
__device__ int   g_chunk_cluster[NCH];
__device__ int   g_chunk_count[NCH];
__device__ int   g_perm[NPAD];                   // sorted item -> original item (-1 = pad)
__device__ float g_W2s[(size_t)D_*NPAD];         // cluster-sorted, padded W2 (26.5 MB)
__device__ float g_Hd[D_*B_];                    // H transposed: [d][b]

// ---------------- k0: zero scratch ----------------
__global__ void k_zero() {
    int t = blockIdx.x*blockDim.x + threadIdx.x;
    if (t < NC*D_) g_S1[t] = 0.f;
    if (t < NC)    { g_icounts[t] = 0; g_cursor[t] = 0; }
    if (t < B_*NC) g_E[t] = 0.f;
    if (t < NCH)   g_chunk_count[t] = 0;
    if (t < NPAD)  g_perm[t] = -1;
}

// ---------------- k1: S1[c][d] = sum_{i in c} W1[i][d]; counts ----------------
// Predicated register accumulation (no per-element atomics).
__global__ void k_s1(const float* __restrict__ W1, const int* __restrict__ cl) {
    __shared__ float s1[NC*D_];
    __shared__ int   sc[NC];
    int tid = threadIdx.x;                     // 256 threads
    for (int i = tid; i < NC*D_; i += 256) s1[i] = 0.f;
    if (tid < NC) sc[tid] = 0;
    __syncthreads();
    int d  = tid & (D_-1);
    int rg = tid >> 6;                         // 4 rows per iteration
    float a[NC];
    int   cnt[NC];
#pragma unroll
    for (int j = 0; j < NC; j++) { a[j] = 0.f; cnt[j] = 0; }
    for (int r = blockIdx.x*4 + rg; r < NIT; r += gridDim.x*4) {
        float v = W1[(size_t)r*D_ + d];
        int   c = cl[r];
#pragma unroll
        for (int j = 0; j < NC; j++) {
            a[j]   += (c == j) ? v : 0.f;
            cnt[j] += (c == j) ? 1 : 0;
        }
    }
#pragma unroll
    for (int j = 0; j < NC; j++) atomicAdd(&s1[j*D_ + d], a[j]);
    if (d == 0) {
#pragma unroll
        for (int j = 0; j < NC; j++) atomicAdd(&sc[j], cnt[j]);
    }
    __syncthreads();
    for (int i = tid; i < NC*D_; i += 256) atomicAdd(&g_S1[i], s1[i]);
    if (tid < NC) atomicAdd(&g_icounts[tid], sc[tid]);
}

// ---------------- k2: padded offsets + chunk LUT (single thread) ----------------
__global__ void k_offsets() {
    if (threadIdx.x == 0 && blockIdx.x == 0) {
        int off = 0;
        for (int c = 0; c < NC; c++) {
            int cnt = g_icounts[c];
            g_cursor[c] = off;
            int nch = (cnt + IT - 1) / IT;
            int chbase = off / IT;
            for (int j = 0; j < nch; j++) {
                g_chunk_cluster[chbase + j] = c;
                int rem = cnt - j*IT;
                g_chunk_count[chbase + j] = rem < IT ? rem : IT;
            }
            off += nch * IT;
        }
    }
}

// ---------------- k3: counting-sort scatter (CTA-aggregated) ----------------
__global__ void k_scatter(const int* __restrict__ cl) {
    __shared__ int lc[NC];
    __shared__ int lbase[NC];
    int tid = threadIdx.x;
    if (tid < NC) lc[tid] = 0;
    __syncthreads();
    int i = blockIdx.x*256 + tid;
    int c = 0, lr = 0;
    bool valid = (i < NIT);
    if (valid) { c = cl[i]; lr = atomicAdd(&lc[c], 1); }
    __syncthreads();
    if (tid < NC) lbase[tid] = atomicAdd(&g_cursor[tid], lc[tid]);
    __syncthreads();
    if (valid) g_perm[lbase[c] + lr] = i;
}

// ---------------- k4: physically permute W2 into cluster-sorted order ----------------
__global__ void k_perm(const float* __restrict__ W2) {
    const int P4 = NPAD/4;
    int t = blockIdx.x*blockDim.x + threadIdx.x;
    if (t >= D_*P4) return;
    int dd = t / P4;
    int p  = (t - dd*P4) * 4;
    const float* wrow = W2 + (size_t)dd*NIT;
    int4 s = *reinterpret_cast<const int4*>(&g_perm[p]);
    float4 v;
    v.x = (s.x >= 0) ? wrow[s.x] : 0.f;
    v.y = (s.y >= 0) ? wrow[s.y] : 0.f;
    v.z = (s.z >= 0) ? wrow[s.z] : 0.f;
    v.w = (s.w >= 0) ? wrow[s.w] : 0.f;
    *reinterpret_cast<float4*>(&g_W2s[(size_t)dd*NPAD + p]) = v;
}

// ---------------- k5: H^T[d][b] = sum_c input[b][c] * S1[c][d] ----------------
__global__ void k_h(const float* __restrict__ inp) {
    int t = blockIdx.x*blockDim.x + threadIdx.x;   // t = d*1024 + b
    int b  = t & (B_-1);
    int dd = t >> 10;
    float s = 0.f;
#pragma unroll
    for (int c = 0; c < NC; c++) s += inp[b*NC + c] * g_S1[c*D_ + dd];
    g_Hd[t] = s;
}

// ---------------- k6: main pass — logits + exp + per-cluster reduce ----------------
// CTA tile: 64 users x 256 items (one single-cluster chunk).
// Thread tile: 8 users x 8 items, fp32x2 packed FMA (FFMA2).
__global__ void __launch_bounds__(256) k_main() {
    int bx = blockIdx.x;
    int cnt = g_chunk_count[bx];
    if (cnt == 0) return;
    int cid = g_chunk_cluster[bx];
    int by  = blockIdx.y;
    int tid = threadIdx.x;
    int ix  = tid & 31;          // item group (warp lane)
    int uy  = tid >> 5;          // user group (warp id)
    int u0  = by * UT;

    __shared__ unsigned long long sh_h[D_*UT];     // 32 KB, [k][u], each h duplicated lo|hi
    __shared__ float4 sh_w[KS*(IT/4)];             // 8 KB,  [kk][item/4]

    for (int idx = tid; idx < D_*UT; idx += 256) {
        int k = idx >> 6, u = idx & (UT-1);
        unsigned int hv = __float_as_uint(g_Hd[k*B_ + u0 + u]);
        sh_h[idx] = (unsigned long long)hv | ((unsigned long long)hv << 32);
    }

    unsigned long long acc[8][4];
#pragma unroll
    for (int u = 0; u < 8; u++)
#pragma unroll
        for (int p = 0; p < 4; p++) acc[u][p] = 0ull;

    const float* wbase = g_W2s + (size_t)bx * IT;

    for (int kc = 0; kc < D_/KS; kc++) {
        __syncthreads();
#pragma unroll
        for (int s = 0; s < 2; s++) {
            int slot = tid + s*256;
            int kk = slot >> 6;
            int c4 = slot & 63;
            sh_w[kk*64 + c4] =
                *reinterpret_cast<const float4*>(wbase + (size_t)(kc*KS + kk)*NPAD + c4*4);
        }
        __syncthreads();
#pragma unroll
        for (int kk = 0; kk < KS; kk++) {
            int k = kc*KS + kk;
            const ulonglong2* hp =
                reinterpret_cast<const ulonglong2*>(&sh_h[k*UT + uy*8]);
            ulonglong2 h01 = hp[0], h23 = hp[1], h45 = hp[2], h67 = hp[3];
            const ulonglong2* wp =
                reinterpret_cast<const ulonglong2*>(&sh_w[kk*64 + ix*2]);
            ulonglong2 w01 = wp[0], w23 = wp[1];
            unsigned long long hu[8] = {h01.x,h01.y,h23.x,h23.y,h45.x,h45.y,h67.x,h67.y};
            unsigned long long wv[4] = {w01.x,w01.y,w23.x,w23.y};
#pragma unroll
            for (int u = 0; u < 8; u++)
#pragma unroll
                for (int p = 0; p < 4; p++)
                    asm("fma.rn.f32x2 %0, %1, %2, %0;"
                        : "+l"(acc[u][p]) : "l"(hu[u]), "l"(wv[p]));
        }
    }

    // epilogue: exp + masked warp reduce (whole chunk is one cluster)
    int ibl = ix * 8;
#pragma unroll
    for (int u = 0; u < 8; u++) {
        float s = 0.f;
#pragma unroll
        for (int p = 0; p < 4; p++) {
            float lo = __uint_as_float((unsigned int)acc[u][p]);
            float hi = __uint_as_float((unsigned int)(acc[u][p] >> 32));
            if (ibl + 2*p     < cnt) s += __expf(lo);
            if (ibl + 2*p + 1 < cnt) s += __expf(hi);
        }
#pragma unroll
        for (int o = 16; o > 0; o >>= 1) s += __shfl_down_sync(0xffffffffu, s, o);
        if (ix == 0) atomicAdd(&g_E[(u0 + uy*8 + u)*NC + cid], s);
    }
}

// ---------------- k7: finalize out[b][c] = E/(Z * max(cnt,1)) ----------------
__global__ void k_final(float* __restrict__ out) {
    int b = blockIdx.x*blockDim.x + threadIdx.x;
    if (b >= B_) return;
    float e[NC]; float z = 0.f;
#pragma unroll
    for (int c = 0; c < NC; c++) { e[c] = g_E[b*NC + c]; z += e[c]; }
    float inv = 1.f / z;
#pragma unroll
    for (int c = 0; c < NC; c++) {
        float cc = (float)g_icounts[c];
        out[b*NC + c] = e[c] * inv / fmaxf(cc, 1.f);
    }
}

// ---------------- launch ----------------
extern "C" void kernel_launch(void* const* d_in, const int* in_sizes, int n_in,
                              void* d_out, int out_size) {
    const float* input_array  = (const float*)d_in[0];   // (1024, 10) f32
    const int*   item_cluster = (const int*)  d_in[1];   // (100000,)  i32
    const float* W1           = (const float*)d_in[2];   // (100000, 64) f32
    const float* W2           = (const float*)d_in[3];   // (64, 100000) f32
    float* out = (float*)d_out;                          // (1024, 10) f32

    k_zero   <<<(NPAD+255)/256, 256>>>();
    k_s1     <<<256, 256>>>(W1, item_cluster);
    k_offsets<<<1, 32>>>();
    k_scatter<<<(NIT+255)/256, 256>>>(item_cluster);
    k_perm   <<<(D_*(NPAD/4)+255)/256, 256>>>(W2);
    k_h      <<<(B_*D_)/256, 256>>>(input_array);
    dim3 g(NCH, B_/UT);
    k_main   <<<g, 256>>>();
    k_final  <<<(B_+255)/256, 256>>>(out);
}

// round 8
// speedup vs baseline: 1.0009x; 1.0009x over previous
#include <cuda_runtime.h>
#include <cstdint>

#define B_    1024
#define NIT   100000
#define NC    10
#define D_    64
#define IT    256                 // items per chunk
#define NCH   404                 // max chunks (sum ceil(cnt/256) <= 401)
#define NPAD  (NCH*IT)            // 103424 padded items
#define UT    64                  // users per CTA in main kernel
#define KS    8                   // k rows staged per phase

// ---------------- device scratch (static, no runtime allocation) ----------------
__device__ float g_S1[NC*D_];                    // cluster-summed W1  (10 x 64)
__device__ int   g_icounts[NC];
__device__ int   g_cursor[NC];
__device__ float g_E[B_*NC];                     // per-(user,cluster) exp sums
__device__ int   g_chunk_cluster[NCH];
__device__ int   g_chunk_count[NCH];
__device__ int   g_perm[NPAD];                   // sorted item -> original item (-1 = pad)
__device__ float g_W2s[(size_t)D_*NPAD];         // cluster-sorted, padded W2 (26.5 MB)
__device__ float g_Hd[D_*B_];                    // H transposed: [d][b]

// ---------------- k0: zero scratch ----------------
__global__ void k_zero() {
    int t = blockIdx.x*blockDim.x + threadIdx.x;
    if (t < NC*D_) g_S1[t] = 0.f;
    if (t < NC)    { g_icounts[t] = 0; g_cursor[t] = 0; }
    if (t < B_*NC) g_E[t] = 0.f;
    if (t < NCH)   g_chunk_count[t] = 0;
    if (t < NPAD)  g_perm[t] = -1;
}

// ---------------- k1: S1[c][d] = sum_{i in c} W1[i][d]; counts ----------------
// Predicated register accumulation (no per-element atomics).
__global__ void k_s1(const float* __restrict__ W1, const int* __restrict__ cl) {
    __shared__ float s1[NC*D_];
    __shared__ int   sc[NC];
    int tid = threadIdx.x;                     // 256 threads
    for (int i = tid; i < NC*D_; i += 256) s1[i] = 0.f;
    if (tid < NC) sc[tid] = 0;
    __syncthreads();
    int d  = tid & (D_-1);
    int rg = tid >> 6;                         // 4 rows per iteration
    float a[NC];
    int   cnt[NC];
#pragma unroll
    for (int j = 0; j < NC; j++) { a[j] = 0.f; cnt[j] = 0; }
    for (int r = blockIdx.x*4 + rg; r < NIT; r += gridDim.x*4) {
        float v = W1[(size_t)r*D_ + d];
        int   c = cl[r];
#pragma unroll
        for (int j = 0; j < NC; j++) {
            a[j]   += (c == j) ? v : 0.f;
            cnt[j] += (c == j) ? 1 : 0;
        }
    }
#pragma unroll
    for (int j = 0; j < NC; j++) atomicAdd(&s1[j*D_ + d], a[j]);
    if (d == 0) {
#pragma unroll
        for (int j = 0; j < NC; j++) atomicAdd(&sc[j], cnt[j]);
    }
    __syncthreads();
    for (int i = tid; i < NC*D_; i += 256) atomicAdd(&g_S1[i], s1[i]);
    if (tid < NC) atomicAdd(&g_icounts[tid], sc[tid]);
}

// ---------------- k2: padded offsets + chunk LUT (single thread) ----------------
__global__ void k_offsets() {
    if (threadIdx.x == 0 && blockIdx.x == 0) {
        int off = 0;
        for (int c = 0; c < NC; c++) {
            int cnt = g_icounts[c];
            g_cursor[c] = off;
            int nch = (cnt + IT - 1) / IT;
            int chbase = off / IT;
            for (int j = 0; j < nch; j++) {
                g_chunk_cluster[chbase + j] = c;
                int rem = cnt - j*IT;
                g_chunk_count[chbase + j] = rem < IT ? rem : IT;
            }
            off += nch * IT;
        }
    }
}

// ---------------- k3: counting-sort scatter (CTA-aggregated) ----------------
__global__ void k_scatter(const int* __restrict__ cl) {
    __shared__ int lc[NC];
    __shared__ int lbase[NC];
    int tid = threadIdx.x;
    if (tid < NC) lc[tid] = 0;
    __syncthreads();
    int i = blockIdx.x*256 + tid;
    int c = 0, lr = 0;
    bool valid = (i < NIT);
    if (valid) { c = cl[i]; lr = atomicAdd(&lc[c], 1); }
    __syncthreads();
    if (tid < NC) lbase[tid] = atomicAdd(&g_cursor[tid], lc[tid]);
    __syncthreads();
    if (valid) g_perm[lbase[c] + lr] = i;
}

// ---------------- k4: physically permute W2 into cluster-sorted order ----------------
__global__ void k_perm(const float* __restrict__ W2) {
    const int P4 = NPAD/4;
    int t = blockIdx.x*blockDim.x + threadIdx.x;
    if (t >= D_*P4) return;
    int dd = t / P4;
    int p  = (t - dd*P4) * 4;
    const float* wrow = W2 + (size_t)dd*NIT;
    int4 s = *reinterpret_cast<const int4*>(&g_perm[p]);
    float4 v;
    v.x = (s.x >= 0) ? wrow[s.x] : 0.f;
    v.y = (s.y >= 0) ? wrow[s.y] : 0.f;
    v.z = (s.z >= 0) ? wrow[s.z] : 0.f;
    v.w = (s.w >= 0) ? wrow[s.w] : 0.f;
    *reinterpret_cast<float4*>(&g_W2s[(size_t)dd*NPAD + p]) = v;
}

// ---------------- k5: H^T[d][b] = sum_c input[b][c] * S1[c][d] ----------------
__global__ void k_h(const float* __restrict__ inp) {
    int t = blockIdx.x*blockDim.x + threadIdx.x;   // t = d*1024 + b
    int b  = t & (B_-1);
    int dd = t >> 10;
    float s = 0.f;
#pragma unroll
    for (int c = 0; c < NC; c++) s += inp[b*NC + c] * g_S1[c*D_ + dd];
    g_Hd[t] = s;
}

// ---------------- k6: main pass — logits + exp + per-cluster reduce ----------------
// CTA tile: 64 users x 256 items (one single-cluster chunk).
// Thread tile: 8 users x 8 items, fp32x2 packed FMA (FFMA2).
__global__ void __launch_bounds__(256) k_main() {
    int bx = blockIdx.x;
    int cnt = g_chunk_count[bx];
    if (cnt == 0) return;
    int cid = g_chunk_cluster[bx];
    int by  = blockIdx.y;
    int tid = threadIdx.x;
    int ix  = tid & 31;          // item group (warp lane)
    int uy  = tid >> 5;          // user group (warp id)
    int u0  = by * UT;

    __shared__ unsigned long long sh_h[D_*UT];     // 32 KB, [k][u], each h duplicated lo|hi
    __shared__ float4 sh_w[KS*(IT/4)];             // 8 KB,  [kk][item/4]

    for (int idx = tid; idx < D_*UT; idx += 256) {
        int k = idx >> 6, u = idx & (UT-1);
        unsigned int hv = __float_as_uint(g_Hd[k*B_ + u0 + u]);
        sh_h[idx] = (unsigned long long)hv | ((unsigned long long)hv << 32);
    }

    unsigned long long acc[8][4];
#pragma unroll
    for (int u = 0; u < 8; u++)
#pragma unroll
        for (int p = 0; p < 4; p++) acc[u][p] = 0ull;

    const float* wbase = g_W2s + (size_t)bx * IT;

    for (int kc = 0; kc < D_/KS; kc++) {
        __syncthreads();
#pragma unroll
        for (int s = 0; s < 2; s++) {
            int slot = tid + s*256;
            int kk = slot >> 6;
            int c4 = slot & 63;
            sh_w[kk*64 + c4] =
                *reinterpret_cast<const float4*>(wbase + (size_t)(kc*KS + kk)*NPAD + c4*4);
        }
        __syncthreads();
#pragma unroll
        for (int kk = 0; kk < KS; kk++) {
            int k = kc*KS + kk;
            const ulonglong2* hp =
                reinterpret_cast<const ulonglong2*>(&sh_h[k*UT + uy*8]);
            ulonglong2 h01 = hp[0], h23 = hp[1], h45 = hp[2], h67 = hp[3];
            const ulonglong2* wp =
                reinterpret_cast<const ulonglong2*>(&sh_w[kk*64 + ix*2]);
            ulonglong2 w01 = wp[0], w23 = wp[1];
            unsigned long long hu[8] = {h01.x,h01.y,h23.x,h23.y,h45.x,h45.y,h67.x,h67.y};
            unsigned long long wv[4] = {w01.x,w01.y,w23.x,w23.y};
#pragma unroll
            for (int u = 0; u < 8; u++)
#pragma unroll
                for (int p = 0; p < 4; p++)
                    asm("fma.rn.f32x2 %0, %1, %2, %0;"
                        : "+l"(acc[u][p]) : "l"(hu[u]), "l"(wv[p]));
        }
    }

    // epilogue: exp + masked warp reduce (whole chunk is one cluster)
    int ibl = ix * 8;
#pragma unroll
    for (int u = 0; u < 8; u++) {
        float s = 0.f;
#pragma unroll
        for (int p = 0; p < 4; p++) {
            float lo = __uint_as_float((unsigned int)acc[u][p]);
            float hi = __uint_as_float((unsigned int)(acc[u][p] >> 32));
            if (ibl + 2*p     < cnt) s += __expf(lo);
            if (ibl + 2*p + 1 < cnt) s += __expf(hi);
        }
#pragma unroll
        for (int o = 16; o > 0; o >>= 1) s += __shfl_down_sync(0xffffffffu, s, o);
        if (ix == 0) atomicAdd(&g_E[(u0 + uy*8 + u)*NC + cid], s);
    }
}

// ---------------- k7: finalize out[b][c] = E/(Z * max(cnt,1)) ----------------
__global__ void k_final(float* __restrict__ out) {
    int b = blockIdx.x*blockDim.x + threadIdx.x;
    if (b >= B_) return;
    float e[NC]; float z = 0.f;
#pragma unroll
    for (int c = 0; c < NC; c++) { e[c] = g_E[b*NC + c]; z += e[c]; }
    float inv = 1.f / z;
#pragma unroll
    for (int c = 0; c < NC; c++) {
        float cc = (float)g_icounts[c];
        out[b*NC + c] = e[c] * inv / fmaxf(cc, 1.f);
    }
}

// ---------------- launch ----------------
extern "C" void kernel_launch(void* const* d_in, const int* in_sizes, int n_in,
                              void* d_out, int out_size) {
    const float* input_array  = (const float*)d_in[0];   // (1024, 10) f32
    const int*   item_cluster = (const int*)  d_in[1];   // (100000,)  i32
    const float* W1           = (const float*)d_in[2];   // (100000, 64) f32
    const float* W2           = (const float*)d_in[3];   // (64, 100000) f32
    float* out = (float*)d_out;                          // (1024, 10) f32

    k_zero   <<<(NPAD+255)/256, 256>>>();
    k_s1     <<<256, 256>>>(W1, item_cluster);
    k_offsets<<<1, 32>>>();
    k_scatter<<<(NIT+255)/256, 256>>>(item_cluster);
    k_perm   <<<(D_*(NPAD/4)+255)/256, 256>>>(W2);
    k_h      <<<(B_*D_)/256, 256>>>(input_array);
    dim3 g(NCH, B_/UT);
    k_main   <<<g, 256>>>();
    k_final  <<<(B_+255)/256, 256>>>(out);
}